// round 5
// baseline (speedup 1.0000x reference)
#include <cuda_runtime.h>
#include <cstdint>

// ---------------------------------------------------------------------------
// EfficientFi VQ-VAE forward, B=1024.  Round 5: oc-pair conv blocking,
// kA+kB fusion, 2-token VQ, 4-way blocked 1x1s.
//  kAB: conv1+relu+pool (smem) -> conv2+relu+pool + pre1x1 -> g_vq,g_i1,g_i2
//  kD : VQ argmin, 2 tokens/thread                         -> g_ind, g_lp
//  kD2: deterministic loss reduction                       -> out[0]
//  kE : gather + trans 1x1 + pose head                     -> g_lat, kp
//  kF : unpool2 + dec1 + relu + unpool1 + dec2             -> r_x
// ---------------------------------------------------------------------------

#define NB 1024
typedef unsigned long long ull;

__device__ unsigned char g_i1[NB * 3200];
__device__ float         g_vq[NB * 3200];
__device__ unsigned char g_i2[NB * 2400];
__device__ int           g_ind[NB * 128];
__device__ float         g_lat[NB * 2400];
__device__ float         g_lp[128];

// ---------------- f32x2 packed helpers (sm_103a) ----------------
static __device__ __forceinline__ ull f2pk(float a, float b) {
    ull r; asm("mov.b64 %0, {%1, %2};" : "=l"(r) : "f"(a), "f"(b)); return r;
}
static __device__ __forceinline__ void f2un(ull v, float& lo, float& hi) {
    asm("mov.b64 {%0, %1}, %2;" : "=f"(lo), "=f"(hi) : "l"(v));
}
static __device__ __forceinline__ ull f2dup(float a) { return f2pk(a, a); }
static __device__ __forceinline__ ull f2mul(ull a, ull b) {
    ull d; asm("mul.rn.f32x2 %0, %1, %2;" : "=l"(d) : "l"(a), "l"(b)); return d;
}
static __device__ __forceinline__ ull f2fma(ull a, ull b, ull c) {
    ull d; asm("fma.rn.f32x2 %0, %1, %2, %3;" : "=l"(d) : "l"(a), "l"(b), "l"(c)); return d;
}
static __device__ __forceinline__ ull f2add(ull a, ull b) {
    ull d; asm("add.rn.f32x2 %0, %1, %2;" : "=l"(d) : "l"(a), "l"(b)); return d;
}
static __device__ __forceinline__ float f2sum(ull v) {
    float lo, hi; f2un(v, lo, hi); return lo + hi;
}
static __device__ __forceinline__ ull f2mid(ull a, ull b) {
    float alo, ahi, blo, bhi; f2un(a, alo, ahi); f2un(b, blo, bhi);
    return f2pk(ahi, blo);
}

// 3x3 conv on a 2x2 patch for TWO output channels sharing the input loads.
// tile origin pre-offset to (2*py)*RW + 2*px; channel stride CH; row width RW.
// Per-oc accumulation order identical to R4 template (ic asc, w0..w8).
template <int NIC, int CH, int RW>
static __device__ __forceinline__ void convp2(const float* __restrict__ tile,
                                              const float* __restrict__ wb0,
                                              const float* __restrict__ wb1,
                                              float b0, float b1, ull* acc) {
    acc[0] = f2dup(b0); acc[1] = acc[0];
    acc[2] = f2dup(b1); acc[3] = acc[2];
#pragma unroll 2
    for (int ic = 0; ic < NIC; ++ic) {
        const float* rp = tile + ic * CH;
        ull A0 = *(const ull*)(rp);          ull B0 = *(const ull*)(rp + 2);
        ull A1 = *(const ull*)(rp + RW);     ull B1 = *(const ull*)(rp + RW + 2);
        ull A2 = *(const ull*)(rp + 2 * RW); ull B2 = *(const ull*)(rp + 2 * RW + 2);
        ull A3 = *(const ull*)(rp + 3 * RW); ull B3 = *(const ull*)(rp + 3 * RW + 2);
        ull M0 = f2mid(A0, B0), M1 = f2mid(A1, B1);
        ull M2 = f2mid(A2, B2), M3 = f2mid(A3, B3);
        const float* wp0 = wb0 + ic * 9;
        const float* wp1 = wb1 + ic * 9;
        ull w;
        w = f2dup(wp0[0]); acc[0] = f2fma(w, A0, acc[0]); acc[1] = f2fma(w, A1, acc[1]);
        w = f2dup(wp0[1]); acc[0] = f2fma(w, M0, acc[0]); acc[1] = f2fma(w, M1, acc[1]);
        w = f2dup(wp0[2]); acc[0] = f2fma(w, B0, acc[0]); acc[1] = f2fma(w, B1, acc[1]);
        w = f2dup(wp0[3]); acc[0] = f2fma(w, A1, acc[0]); acc[1] = f2fma(w, A2, acc[1]);
        w = f2dup(wp0[4]); acc[0] = f2fma(w, M1, acc[0]); acc[1] = f2fma(w, M2, acc[1]);
        w = f2dup(wp0[5]); acc[0] = f2fma(w, B1, acc[0]); acc[1] = f2fma(w, B2, acc[1]);
        w = f2dup(wp0[6]); acc[0] = f2fma(w, A2, acc[0]); acc[1] = f2fma(w, A3, acc[1]);
        w = f2dup(wp0[7]); acc[0] = f2fma(w, M2, acc[0]); acc[1] = f2fma(w, M3, acc[1]);
        w = f2dup(wp0[8]); acc[0] = f2fma(w, B2, acc[0]); acc[1] = f2fma(w, B3, acc[1]);
        w = f2dup(wp1[0]); acc[2] = f2fma(w, A0, acc[2]); acc[3] = f2fma(w, A1, acc[3]);
        w = f2dup(wp1[1]); acc[2] = f2fma(w, M0, acc[2]); acc[3] = f2fma(w, M1, acc[3]);
        w = f2dup(wp1[2]); acc[2] = f2fma(w, B0, acc[2]); acc[3] = f2fma(w, B1, acc[3]);
        w = f2dup(wp1[3]); acc[2] = f2fma(w, A1, acc[2]); acc[3] = f2fma(w, A2, acc[3]);
        w = f2dup(wp1[4]); acc[2] = f2fma(w, M1, acc[2]); acc[3] = f2fma(w, M2, acc[3]);
        w = f2dup(wp1[5]); acc[2] = f2fma(w, B1, acc[2]); acc[3] = f2fma(w, B2, acc[3]);
        w = f2dup(wp1[6]); acc[2] = f2fma(w, A2, acc[2]); acc[3] = f2fma(w, A3, acc[3]);
        w = f2dup(wp1[7]); acc[2] = f2fma(w, M2, acc[2]); acc[3] = f2fma(w, M3, acc[3]);
        w = f2dup(wp1[8]); acc[2] = f2fma(w, B2, acc[2]); acc[3] = f2fma(w, B3, acc[3]);
    }
}

static __device__ __forceinline__ void pool_epi(ull r0, ull r1, float& best, int& bi) {
    float a00, a01, a10, a11;
    f2un(r0, a00, a01); f2un(r1, a10, a11);
    float v00 = fmaxf(a00, 0.f), v01 = fmaxf(a01, 0.f);
    float v10 = fmaxf(a10, 0.f), v11 = fmaxf(a11, 0.f);
    best = v00; bi = 0;
    if (v01 > best) { best = v01; bi = 1; }
    if (v10 > best) { best = v10; bi = 2; }
    if (v11 > best) { best = v11; bi = 3; }
}

// ---------------------------------------------------------------------------
// kAB: conv1+pool -> conv2+pool -> pre 1x1.  grid=1024, block=512.
// smem floats: xp[1452] e1ws[864] e1bs[32] p1p[4608] w2s[27648] b2s[96]
//              zs[2400] pws[12288] pbs[128]  = 49516 (198064 B)
// ---------------------------------------------------------------------------
#define SMEM_AB_FLOATS (1452 + 864 + 32 + 4608 + 27648 + 96 + 2400 + 12288 + 128)
__global__ void __launch_bounds__(512) kAB(const float* __restrict__ x,
                                           const float* __restrict__ e1w,
                                           const float* __restrict__ e1b,
                                           const float* __restrict__ w2,
                                           const float* __restrict__ b2,
                                           const float* __restrict__ pw,
                                           const float* __restrict__ pb) {
    extern __shared__ float sm[];
    float* xp   = sm;            // 3 x 22 x 22
    float* e1ws = xp + 1452;     // 864
    float* e1bs = e1ws + 864;    // 32
    float* p1p  = e1bs + 32;     // 32 x 12 x 12
    float* w2s  = p1p + 4608;    // 27648
    float* b2s  = w2s + 27648;   // 96
    float* zs   = b2s + 96;      // 96 x 25
    float* pws  = zs + 2400;     // 12288
    float* pbs  = pws + 12288;   // 128
    const int bb = blockIdx.x;
    const int tid = threadIdx.x;

    for (int i = tid; i < 1452; i += 512) xp[i] = 0.f;
    for (int i = tid; i < 4608; i += 512) p1p[i] = 0.f;
    __syncthreads();
    for (int i = tid; i < 1200; i += 512) {
        int c = i / 400, r = i % 400, y = r / 20, xx = r % 20;
        xp[c * 484 + (y + 1) * 22 + (xx + 1)] = x[bb * 1200 + i];
    }
    {
        const float4* s4 = (const float4*)e1w;  float4* d4 = (float4*)e1ws;
        for (int i = tid; i < 216; i += 512) d4[i] = s4[i];
    }
    if (tid < 32) e1bs[tid] = e1b[tid];
    {
        const float4* s4 = (const float4*)w2;   float4* d4 = (float4*)w2s;
        for (int i = tid; i < 6912; i += 512) d4[i] = s4[i];
    }
    if (tid < 96) b2s[tid] = b2[tid];
    {
        const float4* s4 = (const float4*)pw;   float4* d4 = (float4*)pws;
        for (int i = tid; i < 3072; i += 512) d4[i] = s4[i];
    }
    if (tid < 128) pbs[tid] = pb[tid];
    __syncthreads();

    // conv1 + relu + pool1: 16 oc-pairs x 100 pool cells = 1600 items
    for (int item = tid; item < 1600; item += 512) {
        const int og = item / 100;
        const int r = item % 100;
        const int py = r / 10, px = r % 10;
        const int oc = og * 2;
        ull acc[4];
        convp2<3, 484, 22>(xp + (2 * py) * 22 + 2 * px,
                           e1ws + oc * 27, e1ws + (oc + 1) * 27,
                           e1bs[oc], e1bs[oc + 1], acc);
        float best; int bi;
        pool_epi(acc[0], acc[1], best, bi);
        p1p[oc * 144 + (py + 1) * 12 + (px + 1)] = best;
        g_i1[bb * 3200 + oc * 100 + r] = (unsigned char)bi;
        pool_epi(acc[2], acc[3], best, bi);
        p1p[(oc + 1) * 144 + (py + 1) * 12 + (px + 1)] = best;
        g_i1[bb * 3200 + (oc + 1) * 100 + r] = (unsigned char)bi;
    }
    __syncthreads();

    // conv2 + relu + pool2: 48 oc-pairs x 25 pool cells = 1200 items
    for (int item = tid; item < 1200; item += 512) {
        const int og = item / 25;
        const int s = item % 25;
        const int py = s / 5, px = s % 5;
        const int oc = og * 2;
        ull acc[4];
        convp2<32, 144, 12>(p1p + (2 * py) * 12 + 2 * px,
                            w2s + oc * 288, w2s + (oc + 1) * 288,
                            b2s[oc], b2s[oc + 1], acc);
        float best; int bi;
        pool_epi(acc[0], acc[1], best, bi);
        zs[oc * 25 + s] = best;
        g_i2[bb * 2400 + oc * 25 + s] = (unsigned char)bi;
        pool_epi(acc[2], acc[3], best, bi);
        zs[(oc + 1) * 25 + s] = best;
        g_i2[bb * 2400 + (oc + 1) * 25 + s] = (unsigned char)bi;
    }
    __syncthreads();

    // pre 1x1: 32 e-quads x 25 = 800 items (4 outputs/item, shared zs loads)
    for (int item = tid; item < 800; item += 512) {
        const int eg = item / 25, s = item % 25;
        const int e0 = eg * 4;
        float a0 = 0.f, a1 = 0.f, a2 = 0.f, a3 = 0.f;
#pragma unroll 4
        for (int c = 0; c < 96; ++c) {
            const float zv = zs[c * 25 + s];
            a0 = fmaf(pws[(e0 + 0) * 96 + c], zv, a0);
            a1 = fmaf(pws[(e0 + 1) * 96 + c], zv, a1);
            a2 = fmaf(pws[(e0 + 2) * 96 + c], zv, a2);
            a3 = fmaf(pws[(e0 + 3) * 96 + c], zv, a3);
        }
        g_vq[bb * 3200 + (e0 + 0) * 25 + s] = a0 + pbs[e0 + 0];
        g_vq[bb * 3200 + (e0 + 1) * 25 + s] = a1 + pbs[e0 + 1];
        g_vq[bb * 3200 + (e0 + 2) * 25 + s] = a2 + pbs[e0 + 2];
        g_vq[bb * 3200 + (e0 + 3) * 25 + s] = a3 + pbs[e0 + 3];
    }
}

// ---------------------------------------------------------------------------
// kD: VQ argmin, 2 tokens/thread. grid=128, block=512. smem 114688 B.
// Row pad 28: [c0..c24, 0.5*||c||^2, 0, 0]; token pad slot25 = -1.
// ---------------------------------------------------------------------------
#define SMEM_D_FLOATS (1024 * 28)
__global__ void __launch_bounds__(512) kD(const float* __restrict__ codebook) {
    extern __shared__ float cb[];
    __shared__ float sred[16];
    const int tid = threadIdx.x;

    for (int j = tid; j < 1024; j += 512) {
        float nrm = 0.f;
#pragma unroll
        for (int k = 0; k < 25; ++k) {
            float v = codebook[j * 25 + k];
            cb[j * 28 + k] = v;
            nrm = fmaf(v, v, nrm);
        }
        cb[j * 28 + 25] = 0.5f * nrm;
        cb[j * 28 + 26] = 0.f;
        cb[j * 28 + 27] = 0.f;
    }
    __syncthreads();

    const int t0 = blockIdx.x * 1024 + tid;   // sibling token: t0 + 512
    ull f0[13], f1[13];
    {
        const float* fv = g_vq + t0 * 25;
#pragma unroll
        for (int i = 0; i < 12; ++i) f0[i] = f2pk(fv[2 * i], fv[2 * i + 1]);
        f0[12] = f2pk(fv[24], -1.0f);
        const float* gv = g_vq + (t0 + 512) * 25;
#pragma unroll
        for (int i = 0; i < 12; ++i) f1[i] = f2pk(gv[2 * i], gv[2 * i + 1]);
        f1[12] = f2pk(gv[24], -1.0f);
    }

    float best0 = -3.402823e38f, best1 = -3.402823e38f;
    int bi0 = 0, bi1 = 0;
    for (int j = 0; j < 1024; ++j) {
        const ulonglong2* row = reinterpret_cast<const ulonglong2*>(cb + j * 28);
        ulonglong2 v0 = row[0], v1 = row[1], v2 = row[2];
        ulonglong2 v3 = row[3], v4 = row[4], v5 = row[5];
        ull v6 = *(const ull*)(cb + j * 28 + 24);   // (c24, 0.5||c||^2)
        ull a0 = f2mul(f0[0], v0.x);
        ull c0 = f2mul(f0[1], v0.y);
        ull a1 = f2mul(f1[0], v0.x);
        ull c1 = f2mul(f1[1], v0.y);
        a0 = f2fma(f0[2], v1.x, a0);  c0 = f2fma(f0[3], v1.y, c0);
        a1 = f2fma(f1[2], v1.x, a1);  c1 = f2fma(f1[3], v1.y, c1);
        a0 = f2fma(f0[4], v2.x, a0);  c0 = f2fma(f0[5], v2.y, c0);
        a1 = f2fma(f1[4], v2.x, a1);  c1 = f2fma(f1[5], v2.y, c1);
        a0 = f2fma(f0[6], v3.x, a0);  c0 = f2fma(f0[7], v3.y, c0);
        a1 = f2fma(f1[6], v3.x, a1);  c1 = f2fma(f1[7], v3.y, c1);
        a0 = f2fma(f0[8], v4.x, a0);  c0 = f2fma(f0[9], v4.y, c0);
        a1 = f2fma(f1[8], v4.x, a1);  c1 = f2fma(f1[9], v4.y, c1);
        a0 = f2fma(f0[10], v5.x, a0); c0 = f2fma(f0[11], v5.y, c0);
        a1 = f2fma(f1[10], v5.x, a1); c1 = f2fma(f1[11], v5.y, c1);
        a0 = f2fma(f0[12], v6, a0);
        a1 = f2fma(f1[12], v6, a1);
        float sc0 = f2sum(f2add(a0, c0));
        float sc1 = f2sum(f2add(a1, c1));
        if (sc0 > best0) { best0 = sc0; bi0 = j; }   // strict > == first-argmin
        if (sc1 > best1) { best1 = sc1; bi1 = j; }
    }
    g_ind[t0] = bi0;
    g_ind[t0 + 512] = bi1;

    // exact commitment-loss contributions
    float ls = 0.f;
    {
        const float* rr = cb + bi0 * 28;
#pragma unroll
        for (int i = 0; i < 12; ++i) {
            float lo, hi; f2un(f0[i], lo, hi);
            float d0 = rr[2 * i] - lo;     ls = fmaf(d0, d0, ls);
            float d1 = rr[2 * i + 1] - hi; ls = fmaf(d1, d1, ls);
        }
        float lo, hi; f2un(f0[12], lo, hi);
        float d = rr[24] - lo; ls = fmaf(d, d, ls);
    }
    {
        const float* rr = cb + bi1 * 28;
#pragma unroll
        for (int i = 0; i < 12; ++i) {
            float lo, hi; f2un(f1[i], lo, hi);
            float d0 = rr[2 * i] - lo;     ls = fmaf(d0, d0, ls);
            float d1 = rr[2 * i + 1] - hi; ls = fmaf(d1, d1, ls);
        }
        float lo, hi; f2un(f1[12], lo, hi);
        float d = rr[24] - lo; ls = fmaf(d, d, ls);
    }
#pragma unroll
    for (int off = 16; off; off >>= 1) ls += __shfl_down_sync(0xffffffffu, ls, off);
    if ((tid & 31) == 0) sred[tid >> 5] = ls;
    __syncthreads();
    if (tid == 0) {
        float s = 0.f;
#pragma unroll
        for (int w = 0; w < 16; ++w) s += sred[w];
        g_lp[blockIdx.x] = s;
    }
}

// kD2: deterministic final loss reduction -> out[0]
__global__ void __launch_bounds__(128) kD2(float* __restrict__ out) {
    __shared__ float sred[4];
    const int tid = threadIdx.x;
    float s = g_lp[tid];
#pragma unroll
    for (int off = 16; off; off >>= 1) s += __shfl_down_sync(0xffffffffu, s, off);
    if ((tid & 31) == 0) sred[tid >> 5] = s;
    __syncthreads();
    if (tid == 0) {
        float t = 0.f;
#pragma unroll
        for (int w = 0; w < 4; ++w) t += sred[w];
        out[0] = t * (0.25f / 3276800.0f);
    }
}

// ---------------------------------------------------------------------------
// kE: gather codes, trans 1x1 (128->96) 4-way blocked, pose head.
// grid=1024, block=512.  smem floats: zr[3200] tws[12288] lat[2400] = 71552 B
// ---------------------------------------------------------------------------
#define SMEM_E_FLOATS (3200 + 12288 + 2400)
#define KP_OFF (1 + 1228800)
__global__ void __launch_bounds__(512) kE(const float* __restrict__ codebook,
                                          const float* __restrict__ tw,
                                          const float* __restrict__ tb,
                                          const float* __restrict__ w1,
                                          const float* __restrict__ b1,
                                          const float* __restrict__ w2,
                                          const float* __restrict__ b2,
                                          float* __restrict__ out) {
    extern __shared__ float sm[];
    float* zr  = sm;            // 128 x 25
    float* tws = zr + 3200;     // 12288
    float* lat = tws + 12288;   // 96 x 25
    __shared__ float part[512];
    __shared__ float hid[32];
    const int bb = blockIdx.x;
    const int tid = threadIdx.x;

    {
        const float4* s4 = (const float4*)tw;  float4* d4 = (float4*)tws;
        for (int i = tid; i < 3072; i += 512) d4[i] = s4[i];
    }
    for (int el = tid; el < 3200; el += 512) {
        int i = el / 25, k = el % 25;
        int ci = g_ind[bb * 128 + i];
        zr[el] = codebook[ci * 25 + k];
    }
    __syncthreads();

    // trans 1x1: 24 oc-quads x 25 = 600 items, shared zr loads
    for (int item = tid; item < 600; item += 512) {
        const int og = item / 25, s = item % 25;
        const int oc = og * 4;
        float a0 = 0.f, a1 = 0.f, a2 = 0.f, a3 = 0.f;
#pragma unroll 4
        for (int i = 0; i < 128; ++i) {
            const float zv = zr[i * 25 + s];
            a0 = fmaf(tws[i * 96 + oc + 0], zv, a0);
            a1 = fmaf(tws[i * 96 + oc + 1], zv, a1);
            a2 = fmaf(tws[i * 96 + oc + 2], zv, a2);
            a3 = fmaf(tws[i * 96 + oc + 3], zv, a3);
        }
        a0 += tb[oc + 0]; a1 += tb[oc + 1]; a2 += tb[oc + 2]; a3 += tb[oc + 3];
        lat[(oc + 0) * 25 + s] = a0; g_lat[bb * 2400 + (oc + 0) * 25 + s] = a0;
        lat[(oc + 1) * 25 + s] = a1; g_lat[bb * 2400 + (oc + 1) * 25 + s] = a1;
        lat[(oc + 2) * 25 + s] = a2; g_lat[bb * 2400 + (oc + 2) * 25 + s] = a2;
        lat[(oc + 3) * 25 + s] = a3; g_lat[bb * 2400 + (oc + 3) * 25 + s] = a3;
    }
    __syncthreads();

    // pose head
    const int warp = tid >> 5, lane = tid & 31;
    float a = 0.f;
    const int fbeg = warp * 150, fend = fbeg + 150;
    for (int f = fbeg; f < fend; ++f) a = fmaf(lat[f], w1[f * 32 + lane], a);
    part[warp * 32 + lane] = a;
    __syncthreads();
    if (tid < 32) {
        float s = b1[tid];
#pragma unroll
        for (int w = 0; w < 16; ++w) s += part[w * 32 + tid];
        hid[tid] = fmaxf(s, 0.f);
    }
    __syncthreads();
    if (tid < 36) {
        float acc = b2[tid];
#pragma unroll
        for (int h = 0; h < 32; ++h) acc = fmaf(hid[h], w2[h * 36 + tid], acc);
        out[KP_OFF + bb * 36 + tid] = acc;
    }
}

// ---------------------------------------------------------------------------
// kF: unpool2 + dec1 (oc-pair) + relu + unpool1 + dec2. grid=1024, block=512.
// smem floats: u2p[13824] w1s[27648] u1[12800] w2s[864] = 220544 B
// ---------------------------------------------------------------------------
#define SMEM_F_FLOATS (13824 + 27648 + 12800 + 864)
__global__ void __launch_bounds__(512) kF(const float* __restrict__ dw1,
                                          const float* __restrict__ db1,
                                          const float* __restrict__ dw2,
                                          const float* __restrict__ db2,
                                          float* __restrict__ out) {
    extern __shared__ float sm[];
    float* u2p = sm;             // 96 x 12 x 12
    float* w1s = u2p + 13824;
    float* u1  = w1s + 27648;    // 32 x 20 x 20
    float* w2s = u1 + 12800;
    __shared__ float b1s[32];
    __shared__ float b2s[3];
    const int bb = blockIdx.x;
    const int tid = threadIdx.x;

    for (int i = tid; i < 13824; i += 512) u2p[i] = 0.f;
    for (int i = tid; i < 12800; i += 512) u1[i] = 0.f;
    __syncthreads();

    for (int el = tid; el < 2400; el += 512) {
        int c = el / 25, s = el % 25, py = s / 5, px = s % 5;
        float v = g_lat[bb * 2400 + el];
        int ii = g_i2[bb * 2400 + el];
        u2p[c * 144 + (2 * py + (ii >> 1) + 1) * 12 + (2 * px + (ii & 1) + 1)] = v;
    }
    {
        const float4* s4 = (const float4*)dw1;  float4* d4 = (float4*)w1s;
        for (int i = tid; i < 6912; i += 512) d4[i] = s4[i];
    }
    {
        const float4* s4 = (const float4*)dw2;  float4* d4 = (float4*)w2s;
        for (int i = tid; i < 216; i += 512) d4[i] = s4[i];
    }
    if (tid < 32) b1s[tid] = db1[tid];
    if (tid < 3) b2s[tid] = db2[tid];
    __syncthreads();

    // dec1: 16 oc-pairs x 25 patches = 400 items; relu; unpool1 scatter
    for (int item = tid; item < 400; item += 512) {
        const int og = item / 25;
        const int s = item % 25;
        const int py = s / 5, px = s % 5;
        const int oc = og * 2;
        ull acc[4];
        convp2<96, 144, 12>(u2p + (2 * py) * 12 + 2 * px,
                            w1s + oc * 864, w1s + (oc + 1) * 864,
                            b1s[oc], b1s[oc + 1], acc);
#pragma unroll
        for (int h = 0; h < 2; ++h) {
            float a[2][2];
            f2un(acc[2 * h + 0], a[0][0], a[0][1]);
            f2un(acc[2 * h + 1], a[1][0], a[1][1]);
            const int o = oc + h;
#pragma unroll
            for (int dy = 0; dy < 2; ++dy)
#pragma unroll
                for (int dx = 0; dx < 2; ++dx) {
                    const int y = 2 * py + dy, xx = 2 * px + dx;
                    float v = fmaxf(a[dy][dx], 0.f);
                    int ii = g_i1[bb * 3200 + o * 100 + y * 10 + xx];
                    u1[o * 400 + (2 * y + (ii >> 1)) * 20 + (2 * xx + (ii & 1))] = v;
                }
        }
    }
    __syncthreads();

    // dec2 conv (32->3, 20x20, pad1)
    for (int o = tid; o < 1200; o += 512) {
        const int oc = o / 400;
        const int r = o % 400;
        const int y = r / 20, x = r % 20;
        float acc = b2s[oc];
        for (int ic = 0; ic < 32; ++ic) {
            const float* wp = w2s + (oc * 32 + ic) * 9;
            const float* up = u1 + ic * 400;
#pragma unroll
            for (int kh = 0; kh < 3; ++kh) {
                const int yy = y + kh - 1;
                if ((unsigned)yy < 20u) {
#pragma unroll
                    for (int kw = 0; kw < 3; ++kw) {
                        const int xx = x + kw - 1;
                        if ((unsigned)xx < 20u)
                            acc = fmaf(wp[kh * 3 + kw], up[yy * 20 + xx], acc);
                    }
                }
            }
        }
        out[1 + bb * 1200 + o] = acc;
    }
}

// ---------------------------------------------------------------------------
extern "C" void kernel_launch(void* const* d_in, const int* in_sizes, int n_in,
                              void* d_out, int out_size) {
    const float* x    = (const float*)d_in[0];
    const float* e1w  = (const float*)d_in[1];
    const float* e1b  = (const float*)d_in[2];
    const float* e2w  = (const float*)d_in[3];
    const float* e2b  = (const float*)d_in[4];
    const float* prew = (const float*)d_in[5];
    const float* preb = (const float*)d_in[6];
    const float* cbk  = (const float*)d_in[7];
    const float* trw  = (const float*)d_in[8];
    const float* trb  = (const float*)d_in[9];
    const float* d1w  = (const float*)d_in[10];
    const float* d1b  = (const float*)d_in[11];
    const float* d2w  = (const float*)d_in[12];
    const float* d2b  = (const float*)d_in[13];
    const float* hw1  = (const float*)d_in[14];
    const float* hb1  = (const float*)d_in[15];
    const float* hw2  = (const float*)d_in[16];
    const float* hb2  = (const float*)d_in[17];
    float* out = (float*)d_out;

    cudaFuncSetAttribute(kAB, cudaFuncAttributeMaxDynamicSharedMemorySize, SMEM_AB_FLOATS * 4);
    cudaFuncSetAttribute(kD, cudaFuncAttributeMaxDynamicSharedMemorySize, SMEM_D_FLOATS * 4);
    cudaFuncSetAttribute(kE, cudaFuncAttributeMaxDynamicSharedMemorySize, SMEM_E_FLOATS * 4);
    cudaFuncSetAttribute(kF, cudaFuncAttributeMaxDynamicSharedMemorySize, SMEM_F_FLOATS * 4);

    kAB<<<NB, 512, SMEM_AB_FLOATS * 4>>>(x, e1w, e1b, e2w, e2b, prew, preb);
    kD<<<128, 512, SMEM_D_FLOATS * 4>>>(cbk);
    kD2<<<1, 128>>>(out);
    kE<<<NB, 512, SMEM_E_FLOATS * 4>>>(cbk, trw, trb, hw1, hb1, hw2, hb2, out);
    kF<<<NB, 512, SMEM_F_FLOATS * 4>>>(d1w, d1b, d2w, d2b, out);
}

// round 7
// speedup vs baseline: 1.2365x; 1.2365x over previous
#include <cuda_runtime.h>
#include <cstdint>

// ---------------------------------------------------------------------------
// EfficientFi VQ-VAE forward, B=1024.  Round 6: R4 arithmetic (decision paths
// byte-identical) + balanced blocks (800), single-wave kD (128x1024),
// f32x2 s-pair trans in kE.
// ---------------------------------------------------------------------------

#define NB 1024
typedef unsigned long long ull;

__device__ float         g_p1[NB * 3200];
__device__ unsigned char g_i1[NB * 3200];
__device__ float         g_vq[NB * 3200];
__device__ unsigned char g_i2[NB * 2400];
__device__ int           g_ind[NB * 128];
__device__ float         g_lat[NB * 2400];
__device__ float         g_lp[128];

// ---------------- f32x2 packed helpers (sm_103a) ----------------
static __device__ __forceinline__ ull f2pk(float a, float b) {
    ull r; asm("mov.b64 %0, {%1, %2};" : "=l"(r) : "f"(a), "f"(b)); return r;
}
static __device__ __forceinline__ void f2un(ull v, float& lo, float& hi) {
    asm("mov.b64 {%0, %1}, %2;" : "=f"(lo), "=f"(hi) : "l"(v));
}
static __device__ __forceinline__ ull f2dup(float a) { return f2pk(a, a); }
static __device__ __forceinline__ ull f2mul(ull a, ull b) {
    ull d; asm("mul.rn.f32x2 %0, %1, %2;" : "=l"(d) : "l"(a), "l"(b)); return d;
}
static __device__ __forceinline__ ull f2fma(ull a, ull b, ull c) {
    ull d; asm("fma.rn.f32x2 %0, %1, %2, %3;" : "=l"(d) : "l"(a), "l"(b), "l"(c)); return d;
}
static __device__ __forceinline__ ull f2add(ull a, ull b) {
    ull d; asm("add.rn.f32x2 %0, %1, %2;" : "=l"(d) : "l"(a), "l"(b)); return d;
}
static __device__ __forceinline__ float f2sum(ull v) {
    float lo, hi; f2un(v, lo, hi); return lo + hi;
}
static __device__ __forceinline__ ull f2mid(ull a, ull b) {
    float alo, ahi, blo, bhi; f2un(a, alo, ahi); f2un(b, blo, bhi);
    return f2pk(ahi, blo);
}

// 3x3 conv on a 2x2 pooled patch (single oc) — IDENTICAL arithmetic to R4.
template <int NIC>
static __device__ __forceinline__ void conv3x3_patch12(const float* __restrict__ tile,
                                                       const float* __restrict__ wbase,
                                                       float bias, ull& acc0, ull& acc1) {
    acc0 = f2dup(bias);
    acc1 = acc0;
#pragma unroll 4
    for (int ic = 0; ic < NIC; ++ic) {
        const float* rp = tile + ic * 144;
        ull A0 = *(const ull*)(rp);      ull B0 = *(const ull*)(rp + 2);
        ull A1 = *(const ull*)(rp + 12); ull B1 = *(const ull*)(rp + 14);
        ull A2 = *(const ull*)(rp + 24); ull B2 = *(const ull*)(rp + 26);
        ull A3 = *(const ull*)(rp + 36); ull B3 = *(const ull*)(rp + 38);
        ull M0 = f2mid(A0, B0), M1 = f2mid(A1, B1);
        ull M2 = f2mid(A2, B2), M3 = f2mid(A3, B3);
        const float* wp = wbase + ic * 9;
        ull w;
        w = f2dup(wp[0]); acc0 = f2fma(w, A0, acc0); acc1 = f2fma(w, A1, acc1);
        w = f2dup(wp[1]); acc0 = f2fma(w, M0, acc0); acc1 = f2fma(w, M1, acc1);
        w = f2dup(wp[2]); acc0 = f2fma(w, B0, acc0); acc1 = f2fma(w, B1, acc1);
        w = f2dup(wp[3]); acc0 = f2fma(w, A1, acc0); acc1 = f2fma(w, A2, acc1);
        w = f2dup(wp[4]); acc0 = f2fma(w, M1, acc0); acc1 = f2fma(w, M2, acc1);
        w = f2dup(wp[5]); acc0 = f2fma(w, B1, acc0); acc1 = f2fma(w, B2, acc1);
        w = f2dup(wp[6]); acc0 = f2fma(w, A2, acc0); acc1 = f2fma(w, A3, acc1);
        w = f2dup(wp[7]); acc0 = f2fma(w, M2, acc0); acc1 = f2fma(w, M3, acc1);
        w = f2dup(wp[8]); acc0 = f2fma(w, B2, acc0); acc1 = f2fma(w, B3, acc1);
    }
}

// ---------------------------------------------------------------------------
// kA: conv1 + relu + pool1.  grid=1024, block=256.  (unchanged from R4)
// ---------------------------------------------------------------------------
__global__ void __launch_bounds__(256) kA(const float* __restrict__ x,
                                          const float* __restrict__ w,
                                          const float* __restrict__ bias) {
    __shared__ float xp[3 * 484];
    __shared__ float ws[864];
    __shared__ float bs[32];
    const int bb = blockIdx.x;
    const int tid = threadIdx.x;

    for (int i = tid; i < 3 * 484; i += 256) xp[i] = 0.f;
    __syncthreads();
    for (int i = tid; i < 1200; i += 256) {
        int c = i / 400, r = i % 400, y = r / 20, xx = r % 20;
        xp[c * 484 + (y + 1) * 22 + (xx + 1)] = x[bb * 1200 + i];
    }
    for (int i = tid; i < 864; i += 256) ws[i] = w[i];
    if (tid < 32) bs[tid] = bias[tid];
    __syncthreads();

    for (int cell = tid; cell < 3200; cell += 256) {
        const int oc = cell / 100;
        const int r = cell % 100;
        const int py = r / 10, px = r % 10;
        float acc[2][2];
        acc[0][0] = acc[0][1] = acc[1][0] = acc[1][1] = bs[oc];
#pragma unroll
        for (int c = 0; c < 3; ++c) {
            const int base = c * 484 + (2 * py) * 22 + 2 * px;
            float in[4][4];
#pragma unroll
            for (int rr = 0; rr < 4; ++rr)
#pragma unroll
                for (int cc = 0; cc < 4; ++cc) in[rr][cc] = xp[base + rr * 22 + cc];
            const float* wp = ws + (oc * 3 + c) * 9;
#pragma unroll
            for (int kh = 0; kh < 3; ++kh)
#pragma unroll
                for (int kw = 0; kw < 3; ++kw) {
                    const float wv = wp[kh * 3 + kw];
#pragma unroll
                    for (int dy = 0; dy < 2; ++dy)
#pragma unroll
                        for (int dx = 0; dx < 2; ++dx)
                            acc[dy][dx] = fmaf(wv, in[dy + kh][dx + kw], acc[dy][dx]);
                }
        }
        float best = -1.f;
        int bi = 0;
#pragma unroll
        for (int dy = 0; dy < 2; ++dy)
#pragma unroll
            for (int dx = 0; dx < 2; ++dx) {
                float v = fmaxf(acc[dy][dx], 0.f);
                int ii = dy * 2 + dx;
                if (v > best) { best = v; bi = ii; }
            }
        g_p1[bb * 3200 + cell] = best;
        g_i1[bb * 3200 + cell] = (unsigned char)bi;
    }
}

// ---------------------------------------------------------------------------
// kB: conv2 + relu + pool2 + pre 1x1.  grid=1024, block=800.
// smem floats: p1p[4608] w2s[27648] b2s[96] zs[2400] pws[12288] pbs[128]
// ---------------------------------------------------------------------------
#define SMEM_B_FLOATS (4608 + 27648 + 96 + 2400 + 12288 + 128)
__global__ void __launch_bounds__(800) kB(const float* __restrict__ w2,
                                          const float* __restrict__ b2,
                                          const float* __restrict__ pw,
                                          const float* __restrict__ pb) {
    extern __shared__ float sm[];
    float* p1p = sm;            // 32 x 12 x 12
    float* w2s = p1p + 4608;
    float* b2s = w2s + 27648;
    float* zs = b2s + 96;       // 96 x 25
    float* pws = zs + 2400;
    float* pbs = pws + 12288;
    const int bb = blockIdx.x;
    const int tid = threadIdx.x;

    for (int i = tid; i < 4608; i += 800) p1p[i] = 0.f;
    __syncthreads();
    for (int i = tid; i < 3200; i += 800) {
        int c = i / 100, r = i % 100, y = r / 10, xx = r % 10;
        p1p[c * 144 + (y + 1) * 12 + (xx + 1)] = g_p1[bb * 3200 + i];
    }
    {
        const float4* s4 = (const float4*)w2;
        float4* d4 = (float4*)w2s;
        for (int i = tid; i < 6912; i += 800) d4[i] = s4[i];
    }
    if (tid < 96) b2s[tid] = b2[tid];
    {
        const float4* s4 = (const float4*)pw;
        float4* d4 = (float4*)pws;
        for (int i = tid; i < 3072; i += 800) d4[i] = s4[i];
    }
    if (tid < 128) pbs[tid] = pb[tid];
    __syncthreads();

    // conv2+pool: 2400 items, exactly 3 per thread
    for (int cell = tid; cell < 2400; cell += 800) {
        const int oc = cell / 25;
        const int s = cell % 25;
        const int py = s / 5, px = s % 5;
        ull acc0, acc1;
        conv3x3_patch12<32>(p1p + (2 * py) * 12 + 2 * px, w2s + oc * 288, b2s[oc], acc0, acc1);
        float a00, a01, a10, a11;
        f2un(acc0, a00, a01); f2un(acc1, a10, a11);
        float v00 = fmaxf(a00, 0.f), v01 = fmaxf(a01, 0.f);
        float v10 = fmaxf(a10, 0.f), v11 = fmaxf(a11, 0.f);
        float best = v00; int bi = 0;
        if (v01 > best) { best = v01; bi = 1; }
        if (v10 > best) { best = v10; bi = 2; }
        if (v11 > best) { best = v11; bi = 3; }
        zs[oc * 25 + s] = best;
        g_i2[bb * 2400 + cell] = (unsigned char)bi;
    }
    __syncthreads();

    // pre 1x1 — arithmetic byte-identical to R4 (feeds VQ argmin!)
    for (int o = tid; o < 3200; o += 800) {
        const int e = o / 25, s = o % 25;
        const float* wp = pws + e * 96;
        float a0 = 0.f, a1 = 0.f, a2 = 0.f, a3 = 0.f;
#pragma unroll 4
        for (int c = 0; c < 96; c += 4) {
            a0 = fmaf(wp[c + 0], zs[(c + 0) * 25 + s], a0);
            a1 = fmaf(wp[c + 1], zs[(c + 1) * 25 + s], a1);
            a2 = fmaf(wp[c + 2], zs[(c + 2) * 25 + s], a2);
            a3 = fmaf(wp[c + 3], zs[(c + 3) * 25 + s], a3);
        }
        g_vq[bb * 3200 + o] = (a0 + a1) + (a2 + a3) + pbs[e];
    }
}

// ---------------------------------------------------------------------------
// kD: VQ argmin. grid=128, block=1024 (single wave). smem 114688 B.
// Per-token arithmetic byte-identical to R4.
// ---------------------------------------------------------------------------
#define SMEM_D_FLOATS (1024 * 28)
__global__ void __launch_bounds__(1024) kD(const float* __restrict__ codebook) {
    extern __shared__ float cb[];
    __shared__ float sred[32];
    const int tid = threadIdx.x;

    if (tid < 1024) {
        const int j = tid;
        float nrm = 0.f;
#pragma unroll
        for (int k = 0; k < 25; ++k) {
            float v = codebook[j * 25 + k];
            cb[j * 28 + k] = v;
            nrm = fmaf(v, v, nrm);
        }
        cb[j * 28 + 25] = 0.5f * nrm;
        cb[j * 28 + 26] = 0.f;
        cb[j * 28 + 27] = 0.f;
    }
    __syncthreads();

    const int t = blockIdx.x * 1024 + tid;
    ull fp[14];
    {
        const float* fv = g_vq + t * 25;
#pragma unroll
        for (int i = 0; i < 12; ++i) fp[i] = f2pk(fv[2 * i], fv[2 * i + 1]);
        fp[12] = f2pk(fv[24], -1.0f);
        fp[13] = f2pk(0.f, 0.f);
    }

    float best = -3.402823e38f;
    int bi = 0;
#pragma unroll 2
    for (int j = 0; j < 1024; ++j) {
        const ulonglong2* row = reinterpret_cast<const ulonglong2*>(cb + j * 28);
        ulonglong2 v0 = row[0], v1 = row[1], v2 = row[2], v3 = row[3];
        ulonglong2 v4 = row[4], v5 = row[5], v6 = row[6];
        ull a = f2mul(fp[0], v0.x);
        ull c = f2mul(fp[1], v0.y);
        a = f2fma(fp[2], v1.x, a);  c = f2fma(fp[3], v1.y, c);
        a = f2fma(fp[4], v2.x, a);  c = f2fma(fp[5], v2.y, c);
        a = f2fma(fp[6], v3.x, a);  c = f2fma(fp[7], v3.y, c);
        a = f2fma(fp[8], v4.x, a);  c = f2fma(fp[9], v4.y, c);
        a = f2fma(fp[10], v5.x, a); c = f2fma(fp[11], v5.y, c);
        a = f2fma(fp[12], v6.x, a); c = f2fma(fp[13], v6.y, c);
        float sc = f2sum(f2add(a, c));
        if (sc > best) { best = sc; bi = j; }  // strict > == first-argmin
    }
    g_ind[t] = bi;

    float ls = 0.f;
    const float* rr = cb + bi * 28;
#pragma unroll
    for (int i = 0; i < 12; ++i) {
        float lo, hi; f2un(fp[i], lo, hi);
        float d0 = rr[2 * i] - lo;     ls = fmaf(d0, d0, ls);
        float d1 = rr[2 * i + 1] - hi; ls = fmaf(d1, d1, ls);
    }
    {
        float lo, hi; f2un(fp[12], lo, hi);
        float d = rr[24] - lo; ls = fmaf(d, d, ls);
    }
#pragma unroll
    for (int off = 16; off; off >>= 1) ls += __shfl_down_sync(0xffffffffu, ls, off);
    if ((tid & 31) == 0) sred[tid >> 5] = ls;
    __syncthreads();
    if (tid == 0) {
        float s = 0.f;
#pragma unroll
        for (int w = 0; w < 32; ++w) s += sred[w];
        g_lp[blockIdx.x] = s;
    }
}

// kD2: deterministic final loss reduction -> out[0]
__global__ void __launch_bounds__(128) kD2(float* __restrict__ out) {
    __shared__ float sred[4];
    const int tid = threadIdx.x;
    float s = g_lp[tid];
#pragma unroll
    for (int off = 16; off; off >>= 1) s += __shfl_down_sync(0xffffffffu, s, off);
    if ((tid & 31) == 0) sred[tid >> 5] = s;
    __syncthreads();
    if (tid == 0) {
        float t = 0.f;
#pragma unroll
        for (int w = 0; w < 4; ++w) t += sred[w];
        out[0] = t * (0.25f / 3276800.0f);
    }
}

// ---------------------------------------------------------------------------
// kE: gather codes, trans 1x1 (128->96) via f32x2 s-pairs, pose head.
// grid=1024, block=512.  smem floats: zr[3328 (stride 26)] tws[12288] lat[2400]
// ---------------------------------------------------------------------------
#define SMEM_E_FLOATS (3328 + 12288 + 2400)
#define KP_OFF (1 + 1228800)
__global__ void __launch_bounds__(512) kE(const float* __restrict__ codebook,
                                          const float* __restrict__ tw,
                                          const float* __restrict__ tb,
                                          const float* __restrict__ w1,
                                          const float* __restrict__ b1,
                                          const float* __restrict__ w2,
                                          const float* __restrict__ b2,
                                          float* __restrict__ out) {
    extern __shared__ float sm[];
    float* zr  = sm;            // 128 x 26 (col 25 = 0 pad)
    float* tws = zr + 3328;     // 12288
    float* lat = tws + 12288;   // 96 x 25
    __shared__ float part[512];
    __shared__ float hid[32];
    const int bb = blockIdx.x;
    const int tid = threadIdx.x;

    {
        const float4* s4 = (const float4*)tw;
        float4* d4 = (float4*)tws;
        for (int i = tid; i < 3072; i += 512) d4[i] = s4[i];
    }
    for (int el = tid; el < 3328; el += 512) {
        int i = el / 26, k = el % 26;
        float v = 0.f;
        if (k < 25) {
            int ci = g_ind[bb * 128 + i];
            v = codebook[ci * 25 + k];
        }
        zr[el] = v;
    }
    __syncthreads();

    // trans 1x1: 96 oc x 13 s-pairs = 1248 items; packed FFMA2, aligned LDS.64
    for (int item = tid; item < 1248; item += 512) {
        const int oc = item / 13;
        const int s = (item % 13) * 2;
        ull acc = f2pk(0.f, 0.f);
#pragma unroll 4
        for (int i = 0; i < 128; ++i) {
            ull w = f2dup(tws[i * 96 + oc]);
            ull z = *(const ull*)(zr + i * 26 + s);
            acc = f2fma(w, z, acc);
        }
        float lo, hi; f2un(acc, lo, hi);
        const float bo = tb[oc];
        const float v0 = lo + bo;
        lat[oc * 25 + s] = v0;
        g_lat[bb * 2400 + oc * 25 + s] = v0;
        if (s + 1 < 25) {
            const float v1 = hi + bo;
            lat[oc * 25 + s + 1] = v1;
            g_lat[bb * 2400 + oc * 25 + s + 1] = v1;
        }
    }
    __syncthreads();

    // pose head
    const int warp = tid >> 5, lane = tid & 31;
    float a = 0.f;
    const int fbeg = warp * 150, fend = fbeg + 150;
    for (int f = fbeg; f < fend; ++f) a = fmaf(lat[f], w1[f * 32 + lane], a);
    part[warp * 32 + lane] = a;
    __syncthreads();
    if (tid < 32) {
        float s = b1[tid];
#pragma unroll
        for (int w = 0; w < 16; ++w) s += part[w * 32 + tid];
        hid[tid] = fmaxf(s, 0.f);
    }
    __syncthreads();
    if (tid < 36) {
        float acc = b2[tid];
#pragma unroll
        for (int h = 0; h < 32; ++h) acc = fmaf(hid[h], w2[h * 36 + tid], acc);
        out[KP_OFF + bb * 36 + tid] = acc;
    }
}

// ---------------------------------------------------------------------------
// kF: unpool2 + dec1 + relu + unpool1 + dec2.  grid=1024, block=800.
// smem floats: u2p[13824] w1s[27648] u1[12800] w2s[864] = 220544 B
// ---------------------------------------------------------------------------
#define SMEM_F_FLOATS (13824 + 27648 + 12800 + 864)
__global__ void __launch_bounds__(800) kF(const float* __restrict__ dw1,
                                          const float* __restrict__ db1,
                                          const float* __restrict__ dw2,
                                          const float* __restrict__ db2,
                                          float* __restrict__ out) {
    extern __shared__ float sm[];
    float* u2p = sm;             // 96 x 12 x 12
    float* w1s = u2p + 13824;
    float* u1  = w1s + 27648;    // 32 x 20 x 20
    float* w2s = u1 + 12800;
    __shared__ float b1s[32];
    __shared__ float b2s[3];
    const int bb = blockIdx.x;
    const int tid = threadIdx.x;

    for (int i = tid; i < 13824; i += 800) u2p[i] = 0.f;
    for (int i = tid; i < 12800; i += 800) u1[i] = 0.f;
    __syncthreads();

    for (int el = tid; el < 2400; el += 800) {
        int c = el / 25, s = el % 25, py = s / 5, px = s % 5;
        float v = g_lat[bb * 2400 + el];
        int ii = g_i2[bb * 2400 + el];
        u2p[c * 144 + (2 * py + (ii >> 1) + 1) * 12 + (2 * px + (ii & 1) + 1)] = v;
    }
    {
        const float4* s4 = (const float4*)dw1;
        float4* d4 = (float4*)w1s;
        for (int i = tid; i < 6912; i += 800) d4[i] = s4[i];
    }
    {
        const float4* s4 = (const float4*)dw2;
        float4* d4 = (float4*)w2s;
        for (int i = tid; i < 216; i += 800) d4[i] = s4[i];
    }
    if (tid < 32) b1s[tid] = db1[tid];
    if (tid < 3) b2s[tid] = db2[tid];
    __syncthreads();

    // dec1: 800 items, exactly 1 per thread; relu; unpool1 scatter
    {
        const int p = tid;
        const int oc = p / 25;
        const int pr = p % 25;
        const int py = pr / 5, px = pr % 5;
        ull acc0, acc1;
        conv3x3_patch12<96>(u2p + (2 * py) * 12 + 2 * px, w1s + oc * 864, b1s[oc], acc0, acc1);
        float a[2][2];
        f2un(acc0, a[0][0], a[0][1]);
        f2un(acc1, a[1][0], a[1][1]);
#pragma unroll
        for (int dy = 0; dy < 2; ++dy)
#pragma unroll
            for (int dx = 0; dx < 2; ++dx) {
                const int y = 2 * py + dy, x = 2 * px + dx;
                float v = fmaxf(a[dy][dx], 0.f);
                int ii = g_i1[bb * 3200 + oc * 100 + y * 10 + x];
                u1[oc * 400 + (2 * y + (ii >> 1)) * 20 + (2 * x + (ii & 1))] = v;
            }
    }
    __syncthreads();

    // dec2 conv (32->3, 20x20, pad1)
    for (int o = tid; o < 1200; o += 800) {
        const int oc = o / 400;
        const int r = o % 400;
        const int y = r / 20, x = r % 20;
        float acc = b2s[oc];
        for (int ic = 0; ic < 32; ++ic) {
            const float* wp = w2s + (oc * 32 + ic) * 9;
            const float* up = u1 + ic * 400;
#pragma unroll
            for (int kh = 0; kh < 3; ++kh) {
                const int yy = y + kh - 1;
                if ((unsigned)yy < 20u) {
#pragma unroll
                    for (int kw = 0; kw < 3; ++kw) {
                        const int xx = x + kw - 1;
                        if ((unsigned)xx < 20u)
                            acc = fmaf(wp[kh * 3 + kw], up[yy * 20 + xx], acc);
                    }
                }
            }
        }
        out[1 + bb * 1200 + o] = acc;
    }
}

// ---------------------------------------------------------------------------
extern "C" void kernel_launch(void* const* d_in, const int* in_sizes, int n_in,
                              void* d_out, int out_size) {
    const float* x    = (const float*)d_in[0];
    const float* e1w  = (const float*)d_in[1];
    const float* e1b  = (const float*)d_in[2];
    const float* e2w  = (const float*)d_in[3];
    const float* e2b  = (const float*)d_in[4];
    const float* prew = (const float*)d_in[5];
    const float* preb = (const float*)d_in[6];
    const float* cbk  = (const float*)d_in[7];
    const float* trw  = (const float*)d_in[8];
    const float* trb  = (const float*)d_in[9];
    const float* d1w  = (const float*)d_in[10];
    const float* d1b  = (const float*)d_in[11];
    const float* d2w  = (const float*)d_in[12];
    const float* d2b  = (const float*)d_in[13];
    const float* hw1  = (const float*)d_in[14];
    const float* hb1  = (const float*)d_in[15];
    const float* hw2  = (const float*)d_in[16];
    const float* hb2  = (const float*)d_in[17];
    float* out = (float*)d_out;

    cudaFuncSetAttribute(kB, cudaFuncAttributeMaxDynamicSharedMemorySize, SMEM_B_FLOATS * 4);
    cudaFuncSetAttribute(kD, cudaFuncAttributeMaxDynamicSharedMemorySize, SMEM_D_FLOATS * 4);
    cudaFuncSetAttribute(kE, cudaFuncAttributeMaxDynamicSharedMemorySize, SMEM_E_FLOATS * 4);
    cudaFuncSetAttribute(kF, cudaFuncAttributeMaxDynamicSharedMemorySize, SMEM_F_FLOATS * 4);

    kA<<<NB, 256>>>(x, e1w, e1b);
    kB<<<NB, 800, SMEM_B_FLOATS * 4>>>(e2w, e2b, prew, preb);
    kD<<<128, 1024, SMEM_D_FLOATS * 4>>>(cbk);
    kD2<<<1, 128>>>(out);
    kE<<<NB, 512, SMEM_E_FLOATS * 4>>>(cbk, trw, trb, hw1, hb1, hw2, hb2, out);
    kF<<<NB, 800, SMEM_F_FLOATS * 4>>>(d1w, d1b, d2w, d2b, out);
}